// round 6
// baseline (speedup 1.0000x reference)
#include <cuda_runtime.h>
#include <math.h>
#include <stdint.h>

#define BATCH 16
#define CHAN  256
#define HH    64
#define WW    64
#define HWSZ  4096
#define NHW   65536   // BATCH*HH*WW
#define EPSBN 1e-5f

// ---------------- scratch (device globals; no allocation allowed) ----------------
__device__ float g_t1[BATCH*CHAN*HWSZ];                   // conv1 output (fp32)
__device__ float g_u [BATCH*CHAN*HWSZ];                   // conv2 output (pre-bn2)
__device__ float g_v [BATCH*CHAN*HWSZ];                   // shortcut output (pre-bns)
__device__ __align__(16) uint32_t g_xm[BATCH*CHAN*HWSZ];  // x*mod tf32
__device__ __align__(16) uint32_t g_w2t [CHAN*CHAN];      // w_conv2^T tf32 [ci][co]
__device__ __align__(16) uint32_t g_wsct[CHAN*CHAN];      // w_sc^T   tf32 [ci][co]
__device__ __align__(16) uint32_t g_w1t[9*CHAN*CHAN];     // w_conv1 tf32 [tap][ci][co]
__device__ float g_spatial[BATCH*CHAN];
__device__ float g_mod    [BATCH*CHAN];
// [0:C) sum_t1, [C:2C) sq_t1, [2C:3C) sum_u, [3C:4C) sq_u, [4C:5C) sum_v, [5C:6C) sq_v
__device__ float g_stats[6*CHAN];

__device__ __forceinline__ float sigmoidf_(float z) { return 1.f / (1.f + expf(-z)); }
__device__ __forceinline__ float siluf_(float z)    { return z / (1.f + expf(-z)); }

__device__ __forceinline__ uint32_t f2tf32(float f) {
    uint32_t u;
    asm("cvt.rna.tf32.f32 %0, %1;" : "=r"(u) : "f"(f));
    return u;
}

__device__ __forceinline__ void mma_tf32(float* c, uint32_t a0, uint32_t a1,
                                         uint32_t a2, uint32_t a3,
                                         uint32_t b0, uint32_t b1) {
    asm volatile(
        "mma.sync.aligned.m16n8k8.row.col.f32.tf32.tf32.f32 "
        "{%0,%1,%2,%3}, {%4,%5,%6,%7}, {%8,%9}, {%0,%1,%2,%3};"
        : "+f"(c[0]), "+f"(c[1]), "+f"(c[2]), "+f"(c[3])
        : "r"(a0), "r"(a1), "r"(a2), "r"(a3), "r"(b0), "r"(b1));
}

// ---------------- zero the stats accumulators ----------------
__global__ void k_zero_stats() {
    int i = blockIdx.x * blockDim.x + threadIdx.x;
    if (i < 6*CHAN) g_stats[i] = 0.f;
}

// ---------------- spatial proj via edge-sum decomposition (one pass) ----------------
__global__ void k_spatial(const float* __restrict__ x, const float* __restrict__ w_ch) {
    int bc = blockIdx.x;
    int c  = bc & (CHAN-1);
    const float* xp = x + (size_t)bc * HWSZ;
    int tid = threadIdx.x;
    int w = tid & 63;

    float T = 0.f, R0 = 0.f, R1 = 0.f, C0 = 0.f, C1 = 0.f;
    for (int i = tid; i < HWSZ; i += 256) {
        int h = i >> 6;
        float v = xp[i];
        T += v;
        if (h == 0)  R0 += v;
        if (h == 63) R1 += v;
        if (w == 0)  C0 += v;
        if (w == 63) C1 += v;
    }
    __shared__ float red[5];
    if (tid < 5) red[tid] = 0.f;
    __syncthreads();
#pragma unroll
    for (int o = 16; o > 0; o >>= 1) {
        T  += __shfl_xor_sync(0xffffffffu, T,  o);
        R0 += __shfl_xor_sync(0xffffffffu, R0, o);
        R1 += __shfl_xor_sync(0xffffffffu, R1, o);
        C0 += __shfl_xor_sync(0xffffffffu, C0, o);
        C1 += __shfl_xor_sync(0xffffffffu, C1, o);
    }
    if ((tid & 31) == 0) {
        atomicAdd(&red[0], T);
        atomicAdd(&red[1], R0);
        atomicAdd(&red[2], R1);
        atomicAdd(&red[3], C0);
        atomicAdd(&red[4], C1);
    }
    __syncthreads();
    if (tid == 0) {
        float Tt = red[0], tR0 = red[1], tR1 = red[2], tC0 = red[3], tC1 = red[4];
        float c00 = xp[0], c0W = xp[63], cH0 = xp[63*64], cHW = xp[4095];
        float acc = 0.f;
#pragma unroll
        for (int t = 0; t < 9; t++) {
            int dy = t / 3 - 1, dx = t % 3 - 1;
            float s = Tt;
            if (dy == 1)  s -= tR0; else if (dy == -1) s -= tR1;
            if (dx == 1)  s -= tC0; else if (dx == -1) s -= tC1;
            if (dy == 1  && dx == 1)  s += c00;
            if (dy == 1  && dx == -1) s += c0W;
            if (dy == -1 && dx == 1)  s += cH0;
            if (dy == -1 && dx == -1) s += cHW;
            acc += w_ch[c*9 + t] * s;
        }
        g_spatial[bc] = acc * (1.f / (float)HWSZ);
    }
}

// ---------------- gate MLP -> g_mod ----------------
__global__ void k_mod(const float* __restrict__ dce, const float* __restrict__ w_dce,
                      const float* __restrict__ b_dce, const float* __restrict__ w_sh,
                      const float* __restrict__ b_sh, const float* __restrict__ w_ex,
                      const float* __restrict__ b_ex) {
    int b = blockIdx.x;
    int t = threadIdx.x;                 // 128 threads
    __shared__ float pooled[128];
    __shared__ float mbuf[256];
    __shared__ float hbuf[128];

    {
        float s = 0.f;
        const float* dp = dce + (size_t)b * 100 * 128 + t;
        for (int l = 0; l < 100; l++) s += dp[l * 128];
        pooled[t] = s * 0.01f;
    }
    __syncthreads();

    for (int co = t; co < 256; co += 128) {
        float a = b_dce[co];
        const float* wr = w_dce + (size_t)co * 128;
        for (int j = 0; j < 128; j++) a += pooled[j] * wr[j];
        mbuf[co] = a * g_spatial[b*CHAN + co];
    }
    __syncthreads();

    {
        float a = b_sh[t];
        const float* wr = w_sh + (size_t)t * 256;
        for (int i = 0; i < 256; i++) a += mbuf[i] * wr[i];
        hbuf[t] = fmaxf(a, 0.f);
    }
    __syncthreads();

    for (int co = t; co < 256; co += 128) {
        float a = b_ex[co];
        const float* wr = w_ex + (size_t)co * 128;
        for (int i = 0; i < 128; i++) a += hbuf[i] * wr[i];
        g_mod[b*CHAN + co] = sigmoidf_(a);
    }
}

// ---------------- transpose 1x1 weights (to tf32) ----------------
__global__ void k_transpose(const float* __restrict__ w2, const float* __restrict__ wsc) {
    int idx = blockIdx.x * blockDim.x + threadIdx.x;
    if (idx >= CHAN*CHAN) return;
    int co = idx >> 8, ci = idx & 255;
    g_w2t [ci*CHAN + co] = f2tf32(w2 [idx]);
    g_wsct[ci*CHAN + co] = f2tf32(wsc[idx]);
}

// ---------------- conv1 weights to [tap][ci][co], tf32 ----------------
__global__ void k_w1t(const float* __restrict__ w1) {
    int idx = blockIdx.x * blockDim.x + threadIdx.x;
    if (idx >= 9*CHAN*CHAN) return;
    int tap = idx >> 16;
    int rem = idx & 65535;
    int ci  = rem >> 8;
    int co  = rem & 255;
    g_w1t[idx] = f2tf32(w1[(size_t)co*2304 + ci*9 + tap]);
}

// ---------------- xm = tf32(x*mod), materialized once ----------------
__global__ void k_xm(const float* __restrict__ x) {
    int i4 = blockIdx.x * blockDim.x + threadIdx.x;
    size_t base = (size_t)i4 * 4;
    if (base >= (size_t)BATCH*CHAN*HWSZ) return;
    int c = (int)((base >> 12) & 255);
    int b = (int)(base >> 20);
    float mv = g_mod[b*CHAN + c];
    float4 xv = *(const float4*)&x[base];
    uint4 m;
    m.x = f2tf32(xv.x * mv);
    m.y = f2tf32(xv.y * mv);
    m.z = f2tf32(xv.z * mv);
    m.w = f2tf32(xv.w * mv);
    *reinterpret_cast<uint4*>(&g_xm[base]) = m;
}

// ---------------- conv1 via tf32 mma.sync: 9 shifted GEMMs ----------------
#define PPITCH 180                         // uint2 per pair-channel patch (18*10)
#define BPITCH 132                         // uint2 per B row (128 couts + pad)
#define CONV_SMEM_BYTES ((8*PPITCH + 72*BPITCH) * 8)   // 87552
__global__ void __launch_bounds__(256) k_conv1_mma() {
    extern __shared__ uint2 sm2[];
    uint2* p2 = sm2;                 // [pair 0..7][18*10]
    uint2* b2 = sm2 + 8*PPITCH;      // [tap*8 + kh*4 + tq][128 co + pad]

    __shared__ float s_sum[128], s_sq[128];

    int b    = blockIdx.z;
    int co0  = blockIdx.y * 128;
    int tile = blockIdx.x;
    int th0  = (tile >> 3) * 16;
    int tw0  = (tile & 7) * 8;

    int tid  = threadIdx.x;
    int warp = tid >> 5;
    int lane = tid & 31;
    int gid  = lane >> 2;
    int tq   = lane & 3;
    int wm   = warp & 3;
    int wn   = warp >> 2;

    if (tid < 128) { s_sum[tid] = 0.f; s_sq[tid] = 0.f; }

    float acc[2][8][4];
#pragma unroll
    for (int t = 0; t < 2; t++)
#pragma unroll
        for (int j = 0; j < 8; j++)
#pragma unroll
            for (int k = 0; k < 4; k++) acc[t][j][k] = 0.f;

    for (int c0 = 0; c0 < CHAN; c0 += 16) {
        __syncthreads();   // protect smem from previous iteration's reads

        // ---- input halo patch, pair-packed from precomputed g_xm ----
        for (int idx = tid; idx < 8*180; idx += 256) {
            int pr = idx / 180, r = idx - pr*180;
            int iy = r / 10, ix = r - iy*10;
            int kh = pr >> 2, tql = pr & 3;
            int ci = c0 + kh*8 + tql;
            int gh = th0 + iy - 1, gw = tw0 + ix - 1;
            uint32_t va = 0u, vb = 0u;
            if (gh >= 0 && gh < HH && gw >= 0 && gw < WW) {
                size_t gbase = (((size_t)b*CHAN + ci)*HH + gh)*WW + gw;
                va = g_xm[gbase];
                vb = g_xm[gbase + 4*HWSZ];
            }
            p2[pr*PPITCH + r] = make_uint2(va, vb);
        }

        // ---- all 9 taps of B, pair-packed ----
        for (int idx = tid; idx < 2304; idx += 256) {
            int tap = idx >> 8;
            int rem = idx & 255;
            int p   = rem >> 5, co4 = rem & 31;
            int kh  = p >> 2, tql = p & 3;
            int ci  = c0 + kh*8 + tql;
            const uint32_t* gsrc = g_w1t + (size_t)tap*65536 + (size_t)ci*256 + co0 + co4*4;
            uint4 wa = *reinterpret_cast<const uint4*>(gsrc);
            uint4 wb = *reinterpret_cast<const uint4*>(gsrc + 4*256);
            uint2* dst = b2 + (tap*8 + p)*BPITCH + co4*4;
            *reinterpret_cast<uint4*>(dst)     = make_uint4(wa.x, wb.x, wa.y, wb.y);
            *reinterpret_cast<uint4*>(dst + 2) = make_uint4(wa.z, wb.z, wa.w, wb.w);
        }
        __syncthreads();

        // ---- mainloop: 9 taps x 2 k-halves, 16 MMAs each ----
        for (int tap = 0; tap < 9; tap++) {
            int ky = tap / 3, kx = tap - ky*3;
            int abase = ky*10 + gid + kx;
#pragma unroll
            for (int kh = 0; kh < 2; kh++) {
                uint2 aL[2], aH[2];
#pragma unroll
                for (int t = 0; t < 2; t++) {
                    int row0 = wm*4 + t*2;
                    const uint2* ap = p2 + (kh*4 + tq)*PPITCH + row0*10 + abase;
                    aL[t] = ap[0];
                    aH[t] = ap[10];
                }
                const uint2* bp = b2 + (tap*8 + kh*4 + tq)*BPITCH + wn*64 + gid;
#pragma unroll
                for (int j = 0; j < 8; j++) {
                    uint2 bb = bp[j*8];
#pragma unroll
                    for (int t = 0; t < 2; t++)
                        mma_tf32(acc[t][j], aL[t].x, aH[t].x, aL[t].y, aH[t].y, bb.x, bb.y);
                }
            }
        }
    }

    // ---- store + bn1 partial stats ----
    int px = tw0 + gid;
#pragma unroll
    for (int t = 0; t < 2; t++) {
        int gr = th0 + wm*4 + t*2;
#pragma unroll
        for (int j = 0; j < 8; j++) {
            int col = wn*64 + j*8 + tq*2;
            int co  = co0 + col;
            size_t o0 = (((size_t)b*CHAN + co)*HH + gr)*WW + px;
            float c0v = acc[t][j][0], c1v = acc[t][j][1];
            float c2v = acc[t][j][2], c3v = acc[t][j][3];
            g_t1[o0]             = c0v;
            g_t1[o0 + HWSZ]      = c1v;
            g_t1[o0 + WW]        = c2v;
            g_t1[o0 + HWSZ + WW] = c3v;

            float s0 = c0v + c2v;
            float s1 = c1v + c3v;
            float q0 = c0v*c0v + c2v*c2v;
            float q1 = c1v*c1v + c3v*c3v;
#pragma unroll
            for (int o = 4; o < 32; o <<= 1) {
                s0 += __shfl_xor_sync(0xffffffffu, s0, o);
                s1 += __shfl_xor_sync(0xffffffffu, s1, o);
                q0 += __shfl_xor_sync(0xffffffffu, q0, o);
                q1 += __shfl_xor_sync(0xffffffffu, q1, o);
            }
            if (gid == 0) {
                atomicAdd(&s_sum[col],     s0);
                atomicAdd(&s_sum[col + 1], s1);
                atomicAdd(&s_sq [col],     q0);
                atomicAdd(&s_sq [col + 1], q1);
            }
        }
    }
    __syncthreads();
    if (tid < 128) {
        atomicAdd(&g_stats[co0 + tid],        s_sum[tid]);
        atomicAdd(&g_stats[CHAN + co0 + tid], s_sq[tid]);
    }
}

// ---------------- fused 1x1 GEMMs, split by path:
//   path 0: u = w2  @ silu(bn1(t1))   (silu computed in load phase, once)
//   path 1: v = wsc @ g_xm
// grid (B*H = 1024, 2). Block: M=64 pixels (one row), N=256 couts.
// Warps 2(M) x 4(N): warp = 32 pixels x 64 couts.
#define APCH 68    // uint2 pitch for A tile (64 + pad)
#define WPCH 260   // uint2 pitch for W tile (256 couts + pad)  <-- was 132: overflow bug
__global__ void __launch_bounds__(256) k_gemm_mma2(const float* __restrict__ g1,
                                                   const float* __restrict__ be1) {
    __shared__ uint2 sA[16*APCH];
    __shared__ uint2 sW[16*WPCH];
    __shared__ float s_scale[CHAN], s_shift[CHAN];
    __shared__ float s_s[CHAN], s_q[CHAN];

    int bh   = blockIdx.x;
    int b    = bh >> 6;
    int h    = bh & 63;
    int path = blockIdx.y;          // 0 = u, 1 = v
    int tid  = threadIdx.x;
    int warp = tid >> 5;
    int lane = tid & 31;
    int gid  = lane >> 2;
    int tq   = lane & 3;
    int mt   = (warp & 1) * 32;
    int n0   = (warp >> 1) * 64;

    if (path == 0) {
        int c = tid;
        float mean = g_stats[c] * (1.f / (float)NHW);
        float var  = g_stats[CHAN + c] * (1.f / (float)NHW) - mean*mean;
        float sc   = g1[c] * rsqrtf(var + EPSBN);
        s_scale[c] = sc;
        s_shift[c] = be1[c] - mean * sc;
    }
    s_s[tid] = 0.f;
    s_q[tid] = 0.f;

    float acc[2][8][4];
#pragma unroll
    for (int t = 0; t < 2; t++)
#pragma unroll
        for (int j = 0; j < 8; j++)
#pragma unroll
            for (int k = 0; k < 4; k++) acc[t][j][k] = 0.f;

    const uint32_t* wsrc = path ? g_wsct : g_w2t;
    size_t rowb = ((size_t)b*CHAN*HH + h)*WW;

    for (int c0 = 0; c0 < CHAN; c0 += 32) {
        __syncthreads();
        // A tile: 16 pair-rows x 64 pixels
        for (int idx = tid; idx < 1024; idx += 256) {
            int pr = idx >> 6, p = idx & 63;
            int cin = c0 + (pr >> 2)*8 + (pr & 3);
            size_t gi = rowb + (size_t)cin*HWSZ + p;
            uint2 val;
            if (path) {
                val.x = g_xm[gi];
                val.y = g_xm[gi + 4*HWSZ];
            } else {
                float z0 = siluf_(fmaf(g_t1[gi],          s_scale[cin],   s_shift[cin]));
                float z1 = siluf_(fmaf(g_t1[gi + 4*HWSZ], s_scale[cin+4], s_shift[cin+4]));
                val.x = f2tf32(z0);
                val.y = f2tf32(z1);
            }
            sA[pr*APCH + p] = val;
        }
        // W tile: 16 pair-rows x 256 couts (pair-packed)
        for (int idx = tid; idx < 1024; idx += 256) {
            int pr = idx >> 6, c4 = idx & 63;
            int cin = c0 + (pr >> 2)*8 + (pr & 3);
            const uint32_t* src = wsrc + (size_t)cin*CHAN + c4*4;
            uint4 wa = *reinterpret_cast<const uint4*>(src);
            uint4 wb = *reinterpret_cast<const uint4*>(src + 4*CHAN);
            uint2* dst = sW + pr*WPCH + c4*4;
            *reinterpret_cast<uint4*>(dst)     = make_uint4(wa.x, wb.x, wa.y, wb.y);
            *reinterpret_cast<uint4*>(dst + 2) = make_uint4(wa.z, wb.z, wa.w, wb.w);
        }
        __syncthreads();

#pragma unroll
        for (int kh = 0; kh < 4; kh++) {
            uint2 aL[2], aH[2];
#pragma unroll
            for (int t = 0; t < 2; t++) {
                const uint2* ap = sA + (kh*4 + tq)*APCH + mt + t*16 + gid;
                aL[t] = ap[0];
                aH[t] = ap[8];
            }
            const uint2* bp = sW + (kh*4 + tq)*WPCH + n0 + gid;
#pragma unroll
            for (int j = 0; j < 8; j++) {
                uint2 bb = bp[j*8];
#pragma unroll
                for (int t = 0; t < 2; t++)
                    mma_tf32(acc[t][j], aL[t].x, aH[t].x, aL[t].y, aH[t].y, bb.x, bb.y);
            }
        }
    }

    float* gout = path ? g_v : g_u;
#pragma unroll
    for (int t = 0; t < 2; t++) {
        int p = mt + t*16 + gid;
#pragma unroll
        for (int j = 0; j < 8; j++) {
            int co = n0 + j*8 + tq*2;
            size_t o0 = (((size_t)b*CHAN + co)*HH + h)*WW + p;
            float c0v = acc[t][j][0], c1v = acc[t][j][1];
            float c2v = acc[t][j][2], c3v = acc[t][j][3];
            gout[o0]            = c0v;
            gout[o0 + HWSZ]     = c1v;   // co+1
            gout[o0 + 8]        = c2v;   // p+8
            gout[o0 + HWSZ + 8] = c3v;

            float s0 = c0v + c2v;
            float s1 = c1v + c3v;
            float q0 = c0v*c0v + c2v*c2v;
            float q1 = c1v*c1v + c3v*c3v;
#pragma unroll
            for (int o = 4; o < 32; o <<= 1) {
                s0 += __shfl_xor_sync(0xffffffffu, s0, o);
                s1 += __shfl_xor_sync(0xffffffffu, s1, o);
                q0 += __shfl_xor_sync(0xffffffffu, q0, o);
                q1 += __shfl_xor_sync(0xffffffffu, q1, o);
            }
            if (gid == 0) {
                atomicAdd(&s_s[co],     s0);
                atomicAdd(&s_s[co + 1], s1);
                atomicAdd(&s_q[co],     q0);
                atomicAdd(&s_q[co + 1], q1);
            }
        }
    }
    __syncthreads();
    {
        int soff = 2*CHAN + 2*CHAN*path;
        atomicAdd(&g_stats[soff + tid],        s_s[tid]);
        atomicAdd(&g_stats[soff + CHAN + tid], s_q[tid]);
    }
}

// ---------------- final: out = silu(bn2(u) + bns(v)) ----------------
__global__ void k_final(float* __restrict__ out,
                        const float* __restrict__ g2, const float* __restrict__ be2,
                        const float* __restrict__ gs, const float* __restrict__ bes) {
    int i4 = blockIdx.x * blockDim.x + threadIdx.x;
    size_t base = (size_t)i4 * 4;
    if (base >= (size_t)BATCH*CHAN*HWSZ) return;
    int c = (int)((base >> 12) & 255);

    float mu = g_stats[2*CHAN + c] * (1.f / (float)NHW);
    float vu = g_stats[3*CHAN + c] * (1.f / (float)NHW) - mu*mu;
    float su = g2[c] * rsqrtf(vu + EPSBN);
    float bu = be2[c] - mu * su;

    float mv = g_stats[4*CHAN + c] * (1.f / (float)NHW);
    float vv = g_stats[5*CHAN + c] * (1.f / (float)NHW) - mv*mv;
    float sv = gs[c] * rsqrtf(vv + EPSBN);
    float bv = bes[c] - mv * sv;

    float4 u = *(const float4*)&g_u[base];
    float4 v = *(const float4*)&g_v[base];
    float4 o;
    {
        float z;
        z = fmaf(u.x, su, bu) + fmaf(v.x, sv, bv); o.x = siluf_(z);
        z = fmaf(u.y, su, bu) + fmaf(v.y, sv, bv); o.y = siluf_(z);
        z = fmaf(u.z, su, bu) + fmaf(v.z, sv, bv); o.z = siluf_(z);
        z = fmaf(u.w, su, bu) + fmaf(v.w, sv, bv); o.w = siluf_(z);
    }
    *(float4*)&out[base] = o;
}

// ---------------- launch ----------------
extern "C" void kernel_launch(void* const* d_in, const int* in_sizes, int n_in,
                              void* d_out, int out_size) {
    const float* x        = (const float*)d_in[0];
    const float* dce      = (const float*)d_in[1];
    const float* w_dce    = (const float*)d_in[2];
    const float* b_dce    = (const float*)d_in[3];
    const float* w_ch     = (const float*)d_in[4];
    const float* w_shrink = (const float*)d_in[5];
    const float* b_shrink = (const float*)d_in[6];
    const float* w_expand = (const float*)d_in[7];
    const float* b_expand = (const float*)d_in[8];
    const float* w_conv1  = (const float*)d_in[9];
    const float* g_bn1    = (const float*)d_in[10];
    const float* be_bn1   = (const float*)d_in[11];
    const float* w_conv2  = (const float*)d_in[12];
    const float* g_bn2    = (const float*)d_in[13];
    const float* be_bn2   = (const float*)d_in[14];
    const float* w_sc     = (const float*)d_in[15];
    const float* g_bns    = (const float*)d_in[16];
    const float* be_bns   = (const float*)d_in[17];
    float* out = (float*)d_out;

    cudaFuncSetAttribute(k_conv1_mma, cudaFuncAttributeMaxDynamicSharedMemorySize,
                         CONV_SMEM_BYTES);

    k_zero_stats<<<6, 256>>>();
    k_spatial<<<BATCH*CHAN, 256>>>(x, w_ch);
    k_mod<<<BATCH, 128>>>(dce, w_dce, b_dce, w_shrink, b_shrink, w_expand, b_expand);
    k_transpose<<<256, 256>>>(w_conv2, w_sc);
    k_w1t<<<(9*CHAN*CHAN + 255)/256, 256>>>(w_conv1);
    k_xm<<<(BATCH*CHAN*HWSZ/4 + 255)/256, 256>>>(x);
    k_conv1_mma<<<dim3(32, 2, BATCH), 256, CONV_SMEM_BYTES>>>();
    k_gemm_mma2<<<dim3(BATCH*HH, 2), 256>>>(g_bn1, be_bn1);
    k_final<<<(BATCH*CHAN*HWSZ/4 + 255)/256, 256>>>(out, g_bn2, be_bn2, g_bns, be_bns);
}

// round 8
// speedup vs baseline: 1.2515x; 1.2515x over previous
#include <cuda_runtime.h>
#include <math.h>
#include <stdint.h>

#define BATCH 16
#define CHAN  256
#define HH    64
#define WW    64
#define HWSZ  4096
#define NHW   65536   // BATCH*HH*WW
#define EPSBN 1e-5f

// ---------------- scratch (device globals; no allocation allowed) ----------------
__device__ float g_t1[BATCH*CHAN*HWSZ];                   // conv1 output (fp32)
__device__ float g_u [BATCH*CHAN*HWSZ];                   // conv2 output (pre-bn2)
__device__ float g_v [BATCH*CHAN*HWSZ];                   // shortcut output (pre-bns)
__device__ __align__(16) uint32_t g_a [BATCH*CHAN*HWSZ];  // silu(bn1(t1)) tf32
__device__ __align__(16) uint32_t g_xm[BATCH*CHAN*HWSZ];  // x*mod tf32
__device__ __align__(16) uint32_t g_w2t [CHAN*CHAN];      // w_conv2^T tf32 [ci][co]
__device__ __align__(16) uint32_t g_wsct[CHAN*CHAN];      // w_sc^T   tf32 [ci][co]
__device__ __align__(16) uint32_t g_w1t[9*CHAN*CHAN];     // w_conv1 tf32 [tap][ci][co]
__device__ float g_spatial[BATCH*CHAN];
__device__ float g_mod    [BATCH*CHAN];
// [0:C) sum_t1, [C:2C) sq_t1, [2C:3C) sum_u, [3C:4C) sq_u, [4C:5C) sum_v, [5C:6C) sq_v
__device__ float g_stats[6*CHAN];

__device__ __forceinline__ float sigmoidf_(float z) { return 1.f / (1.f + expf(-z)); }
__device__ __forceinline__ float siluf_(float z)    { return z / (1.f + expf(-z)); }

__device__ __forceinline__ uint32_t f2tf32(float f) {
    uint32_t u;
    asm("cvt.rna.tf32.f32 %0, %1;" : "=r"(u) : "f"(f));
    return u;
}

__device__ __forceinline__ void mma_tf32(float* c, uint32_t a0, uint32_t a1,
                                         uint32_t a2, uint32_t a3,
                                         uint32_t b0, uint32_t b1) {
    asm volatile(
        "mma.sync.aligned.m16n8k8.row.col.f32.tf32.tf32.f32 "
        "{%0,%1,%2,%3}, {%4,%5,%6,%7}, {%8,%9}, {%0,%1,%2,%3};"
        : "+f"(c[0]), "+f"(c[1]), "+f"(c[2]), "+f"(c[3])
        : "r"(a0), "r"(a1), "r"(a2), "r"(a3), "r"(b0), "r"(b1));
}

__device__ __forceinline__ uint32_t smem_addr_u32(const void* p) {
    uint32_t a;
    asm("{ .reg .u64 t; cvta.to.shared.u64 t, %1; cvt.u32.u64 %0, t; }"
        : "=r"(a) : "l"(p));
    return a;
}
__device__ __forceinline__ void cp_async4_zfill(uint32_t dst, const void* src, int srcsz) {
    asm volatile("cp.async.ca.shared.global [%0], [%1], 4, %2;"
                 :: "r"(dst), "l"(src), "r"(srcsz));
}
__device__ __forceinline__ void cp_async16(uint32_t dst, const void* src) {
    asm volatile("cp.async.cg.shared.global [%0], [%1], 16;" :: "r"(dst), "l"(src));
}
__device__ __forceinline__ void cp_async_commit_wait() {
    asm volatile("cp.async.commit_group;");
    asm volatile("cp.async.wait_group 0;" ::: "memory");
}

// ---------------- zero the stats accumulators ----------------
__global__ void k_zero_stats() {
    int i = blockIdx.x * blockDim.x + threadIdx.x;
    if (i < 6*CHAN) g_stats[i] = 0.f;
}

// ---------------- spatial proj via edge-sum decomposition (one pass) ----------------
__global__ void k_spatial(const float* __restrict__ x, const float* __restrict__ w_ch) {
    int bc = blockIdx.x;
    int c  = bc & (CHAN-1);
    const float* xp = x + (size_t)bc * HWSZ;
    int tid = threadIdx.x;
    int w = tid & 63;

    float T = 0.f, R0 = 0.f, R1 = 0.f, C0 = 0.f, C1 = 0.f;
    for (int i = tid; i < HWSZ; i += 256) {
        int h = i >> 6;
        float v = xp[i];
        T += v;
        if (h == 0)  R0 += v;
        if (h == 63) R1 += v;
        if (w == 0)  C0 += v;
        if (w == 63) C1 += v;
    }
    __shared__ float red[5];
    if (tid < 5) red[tid] = 0.f;
    __syncthreads();
#pragma unroll
    for (int o = 16; o > 0; o >>= 1) {
        T  += __shfl_xor_sync(0xffffffffu, T,  o);
        R0 += __shfl_xor_sync(0xffffffffu, R0, o);
        R1 += __shfl_xor_sync(0xffffffffu, R1, o);
        C0 += __shfl_xor_sync(0xffffffffu, C0, o);
        C1 += __shfl_xor_sync(0xffffffffu, C1, o);
    }
    if ((tid & 31) == 0) {
        atomicAdd(&red[0], T);
        atomicAdd(&red[1], R0);
        atomicAdd(&red[2], R1);
        atomicAdd(&red[3], C0);
        atomicAdd(&red[4], C1);
    }
    __syncthreads();
    if (tid == 0) {
        float Tt = red[0], tR0 = red[1], tR1 = red[2], tC0 = red[3], tC1 = red[4];
        float c00 = xp[0], c0W = xp[63], cH0 = xp[63*64], cHW = xp[4095];
        float acc = 0.f;
#pragma unroll
        for (int t = 0; t < 9; t++) {
            int dy = t / 3 - 1, dx = t % 3 - 1;
            float s = Tt;
            if (dy == 1)  s -= tR0; else if (dy == -1) s -= tR1;
            if (dx == 1)  s -= tC0; else if (dx == -1) s -= tC1;
            if (dy == 1  && dx == 1)  s += c00;
            if (dy == 1  && dx == -1) s += c0W;
            if (dy == -1 && dx == 1)  s += cH0;
            if (dy == -1 && dx == -1) s += cHW;
            acc += w_ch[c*9 + t] * s;
        }
        g_spatial[bc] = acc * (1.f / (float)HWSZ);
    }
}

// ---------------- gate MLP -> g_mod ----------------
__global__ void k_mod(const float* __restrict__ dce, const float* __restrict__ w_dce,
                      const float* __restrict__ b_dce, const float* __restrict__ w_sh,
                      const float* __restrict__ b_sh, const float* __restrict__ w_ex,
                      const float* __restrict__ b_ex) {
    int b = blockIdx.x;
    int t = threadIdx.x;                 // 128 threads
    __shared__ float pooled[128];
    __shared__ float mbuf[256];
    __shared__ float hbuf[128];

    {
        float s = 0.f;
        const float* dp = dce + (size_t)b * 100 * 128 + t;
        for (int l = 0; l < 100; l++) s += dp[l * 128];
        pooled[t] = s * 0.01f;
    }
    __syncthreads();

    for (int co = t; co < 256; co += 128) {
        float a = b_dce[co];
        const float* wr = w_dce + (size_t)co * 128;
        for (int j = 0; j < 128; j++) a += pooled[j] * wr[j];
        mbuf[co] = a * g_spatial[b*CHAN + co];
    }
    __syncthreads();

    {
        float a = b_sh[t];
        const float* wr = w_sh + (size_t)t * 256;
        for (int i = 0; i < 256; i++) a += mbuf[i] * wr[i];
        hbuf[t] = fmaxf(a, 0.f);
    }
    __syncthreads();

    for (int co = t; co < 256; co += 128) {
        float a = b_ex[co];
        const float* wr = w_ex + (size_t)co * 128;
        for (int i = 0; i < 128; i++) a += hbuf[i] * wr[i];
        g_mod[b*CHAN + co] = sigmoidf_(a);
    }
}

// ---------------- transpose 1x1 weights (to tf32) ----------------
__global__ void k_transpose(const float* __restrict__ w2, const float* __restrict__ wsc) {
    int idx = blockIdx.x * blockDim.x + threadIdx.x;
    if (idx >= CHAN*CHAN) return;
    int co = idx >> 8, ci = idx & 255;
    g_w2t [ci*CHAN + co] = f2tf32(w2 [idx]);
    g_wsct[ci*CHAN + co] = f2tf32(wsc[idx]);
}

// ---------------- conv1 weights to [tap][ci][co], tf32 ----------------
__global__ void k_w1t(const float* __restrict__ w1) {
    int idx = blockIdx.x * blockDim.x + threadIdx.x;
    if (idx >= 9*CHAN*CHAN) return;
    int tap = idx >> 16;
    int rem = idx & 65535;
    int ci  = rem >> 8;
    int co  = rem & 255;
    g_w1t[idx] = f2tf32(w1[(size_t)co*2304 + ci*9 + tap]);
}

// ---------------- xm = tf32(x*mod), materialized once ----------------
__global__ void k_xm(const float* __restrict__ x) {
    int i4 = blockIdx.x * blockDim.x + threadIdx.x;
    size_t base = (size_t)i4 * 4;
    if (base >= (size_t)BATCH*CHAN*HWSZ) return;
    int c = (int)((base >> 12) & 255);
    int b = (int)(base >> 20);
    float mv = g_mod[b*CHAN + c];
    float4 xv = *(const float4*)&x[base];
    uint4 m;
    m.x = f2tf32(xv.x * mv);
    m.y = f2tf32(xv.y * mv);
    m.z = f2tf32(xv.z * mv);
    m.w = f2tf32(xv.w * mv);
    *reinterpret_cast<uint4*>(&g_xm[base]) = m;
}

// ---------------- conv1 via tf32 mma.sync: 9 shifted GEMMs, cp.async staging ----------------
// Block tile: M=128 pixels (16 rows x 8 cols), N=128 couts.
// Warps 4(M) x 2(N): each warp M=32 pixels (4 rows), N=64 couts.
#define PSTR 185                          // words per channel patch row (18*10 + pad)
#define BST  132                          // words per B row (128 couts + pad)
#define CONV_SMEM_BYTES ((16*PSTR + 144*BST) * 4)   // 87872
__global__ void __launch_bounds__(256) k_conv1_mma() {
    extern __shared__ __align__(16) uint32_t smw[];
    uint32_t* s_in = smw;                 // [16 ch][185]
    uint32_t* s_b  = smw + 16*PSTR;       // [tap*16 + ci][132]

    __shared__ float s_sum[128], s_sq[128];

    int b    = blockIdx.z;
    int co0  = blockIdx.y * 128;
    int tile = blockIdx.x;
    int th0  = (tile >> 3) * 16;
    int tw0  = (tile & 7) * 8;

    int tid  = threadIdx.x;
    int warp = tid >> 5;
    int lane = tid & 31;
    int gid  = lane >> 2;
    int tq   = lane & 3;
    int wm   = warp & 3;
    int wn   = warp >> 2;

    if (tid < 128) { s_sum[tid] = 0.f; s_sq[tid] = 0.f; }

    uint32_t s_in_a = smem_addr_u32(s_in);
    uint32_t s_b_a  = smem_addr_u32(s_b);

    float acc[2][8][4];
#pragma unroll
    for (int t = 0; t < 2; t++)
#pragma unroll
        for (int j = 0; j < 8; j++)
#pragma unroll
            for (int k = 0; k < 4; k++) acc[t][j][k] = 0.f;

    for (int c0 = 0; c0 < CHAN; c0 += 16) {
        __syncthreads();   // all warps done reading smem from previous iter

        // ---- input halo patch via cp.async (zfill OOB) ----
        for (int idx = tid; idx < 16*180; idx += 256) {
            int ci = idx / 180, r = idx - ci*180;
            int iy = r / 10, ix = r - iy*10;
            int gh = th0 + iy - 1, gw = tw0 + ix - 1;
            bool ok = (gh >= 0) && (gh < HH) && (gw >= 0) && (gw < WW);
            const uint32_t* src = g_xm + (size_t)(b*CHAN + c0 + ci)*HWSZ
                                + (ok ? (gh*WW + gw) : 0);
            cp_async4_zfill(s_in_a + (uint32_t)(ci*PSTR + r)*4u, src, ok ? 4 : 0);
        }
        // ---- all 9 taps of B via 16B cp.async: 18432 words = 4608 x 16B ----
        for (int idx4 = tid; idx4 < 4608; idx4 += 256) {
            int w   = idx4 * 4;
            int tap = w >> 11;            // 2048 words per tap (16ci x 128co)
            int rem = w & 2047;
            int p   = rem >> 7;           // ci 0..15
            int co4 = rem & 127;
            const uint32_t* src = g_w1t + (size_t)tap*65536 + (size_t)(c0+p)*256
                                + co0 + co4;
            cp_async16(s_b_a + (uint32_t)((tap*16 + p)*BST + co4)*4u, src);
        }
        cp_async_commit_wait();
        __syncthreads();

        // ---- mainloop: 9 taps x 2 k-halves, 32 MMAs each ----
        for (int tap = 0; tap < 9; tap++) {
            int ky = tap / 3, kx = tap - ky*3;
#pragma unroll
            for (int kh = 0; kh < 2; kh++) {
                uint32_t a0[2], a1[2], a2[2], a3[2];
#pragma unroll
                for (int t = 0; t < 2; t++) {
                    int arow = (wm*4 + 2*t + ky)*10 + gid + kx;
                    const uint32_t* ap = s_in + (kh*8 + tq)*PSTR + arow;
                    a0[t] = ap[0];
                    a1[t] = ap[10];        // m+8 (next pixel row)
                    a2[t] = ap[4*PSTR];    // k+4
                    a3[t] = ap[4*PSTR + 10];
                }
                const uint32_t* bp = s_b + (tap*16 + kh*8 + tq)*BST + wn*64 + gid;
#pragma unroll
                for (int j = 0; j < 8; j++) {
                    uint32_t b0 = bp[j*8];
                    uint32_t b1 = bp[j*8 + 4*BST];   // k+4
#pragma unroll
                    for (int t = 0; t < 2; t++)
                        mma_tf32(acc[t][j], a0[t], a1[t], a2[t], a3[t], b0, b1);
                }
            }
        }
    }

    // ---- store + bn1 partial stats ----
    int px = tw0 + gid;
#pragma unroll
    for (int t = 0; t < 2; t++) {
        int gr = th0 + wm*4 + t*2;
#pragma unroll
        for (int j = 0; j < 8; j++) {
            int col = wn*64 + j*8 + tq*2;
            int co  = co0 + col;
            size_t o0 = (((size_t)b*CHAN + co)*HH + gr)*WW + px;
            float c0v = acc[t][j][0], c1v = acc[t][j][1];
            float c2v = acc[t][j][2], c3v = acc[t][j][3];
            g_t1[o0]             = c0v;
            g_t1[o0 + HWSZ]      = c1v;   // co+1
            g_t1[o0 + WW]        = c2v;   // row+1
            g_t1[o0 + HWSZ + WW] = c3v;

            float s0 = c0v + c2v;
            float s1 = c1v + c3v;
            float q0 = c0v*c0v + c2v*c2v;
            float q1 = c1v*c1v + c3v*c3v;
#pragma unroll
            for (int o = 4; o < 32; o <<= 1) {
                s0 += __shfl_xor_sync(0xffffffffu, s0, o);
                s1 += __shfl_xor_sync(0xffffffffu, s1, o);
                q0 += __shfl_xor_sync(0xffffffffu, q0, o);
                q1 += __shfl_xor_sync(0xffffffffu, q1, o);
            }
            if (gid == 0) {
                atomicAdd(&s_sum[col],     s0);
                atomicAdd(&s_sum[col + 1], s1);
                atomicAdd(&s_sq [col],     q0);
                atomicAdd(&s_sq [col + 1], q1);
            }
        }
    }
    __syncthreads();
    if (tid < 128) {
        atomicAdd(&g_stats[co0 + tid],        s_sum[tid]);
        atomicAdd(&g_stats[CHAN + co0 + tid], s_sq[tid]);
    }
}

// ---------------- prep: g_a = tf32(silu(bn1(t1))) (MUFU in a bandwidth-bound pass) ----------
__global__ void k_prep(const float* __restrict__ g1, const float* __restrict__ be1) {
    int i4 = blockIdx.x * blockDim.x + threadIdx.x;
    size_t base = (size_t)i4 * 4;
    if (base >= (size_t)BATCH*CHAN*HWSZ) return;
    int c = (int)((base >> 12) & 255);

    float mean = g_stats[c] * (1.f / (float)NHW);
    float var  = g_stats[CHAN + c] * (1.f / (float)NHW) - mean*mean;
    float sc   = g1[c] * rsqrtf(var + EPSBN);
    float sh   = be1[c] - mean * sc;

    float4 t = *(const float4*)&g_t1[base];
    uint4 a;
    a.x = f2tf32(siluf_(fmaf(t.x, sc, sh)));
    a.y = f2tf32(siluf_(fmaf(t.y, sc, sh)));
    a.z = f2tf32(siluf_(fmaf(t.z, sc, sh)));
    a.w = f2tf32(siluf_(fmaf(t.w, sc, sh)));
    *reinterpret_cast<uint4*>(&g_a[base]) = a;
}

// ---------------- fused 1x1 GEMMs, split by path:
//   path 0: u = w2  @ g_a     path 1: v = wsc @ g_xm
// grid (B*H = 1024, 2). Block: M=64 pixels (one row), N=256 couts.
#define APCH 68    // uint2 pitch for A tile (64 + pad)
#define WPCH 260   // uint2 pitch for W tile (256 couts + pad)
__global__ void __launch_bounds__(256) k_gemm_mma2() {
    __shared__ uint2 sA[16*APCH];
    __shared__ uint2 sW[16*WPCH];
    __shared__ float s_s[CHAN], s_q[CHAN];

    int bh   = blockIdx.x;
    int b    = bh >> 6;
    int h    = bh & 63;
    int path = blockIdx.y;          // 0 = u, 1 = v
    int tid  = threadIdx.x;
    int warp = tid >> 5;
    int lane = tid & 31;
    int gid  = lane >> 2;
    int tq   = lane & 3;
    int mt   = (warp & 1) * 32;
    int n0   = (warp >> 1) * 64;

    s_s[tid] = 0.f;
    s_q[tid] = 0.f;

    float acc[2][8][4];
#pragma unroll
    for (int t = 0; t < 2; t++)
#pragma unroll
        for (int j = 0; j < 8; j++)
#pragma unroll
            for (int k = 0; k < 4; k++) acc[t][j][k] = 0.f;

    const uint32_t* wsrc = path ? g_wsct : g_w2t;
    const uint32_t* asrc = path ? g_xm   : g_a;
    size_t rowb = ((size_t)b*CHAN*HH + h)*WW;

    for (int c0 = 0; c0 < CHAN; c0 += 32) {
        __syncthreads();
        // A tile: 16 pair-rows x 64 pixels (pure copy)
        for (int idx = tid; idx < 1024; idx += 256) {
            int pr = idx >> 6, p = idx & 63;
            int cin = c0 + (pr >> 2)*8 + (pr & 3);
            size_t gi = rowb + (size_t)cin*HWSZ + p;
            uint2 val;
            val.x = asrc[gi];
            val.y = asrc[gi + 4*HWSZ];
            sA[pr*APCH + p] = val;
        }
        // W tile: 16 pair-rows x 256 couts (pair-packed)
        for (int idx = tid; idx < 1024; idx += 256) {
            int pr = idx >> 6, c4 = idx & 63;
            int cin = c0 + (pr >> 2)*8 + (pr & 3);
            const uint32_t* src = wsrc + (size_t)cin*CHAN + c4*4;
            uint4 wa = *reinterpret_cast<const uint4*>(src);
            uint4 wb = *reinterpret_cast<const uint4*>(src + 4*CHAN);
            uint2* dst = sW + pr*WPCH + c4*4;
            *reinterpret_cast<uint4*>(dst)     = make_uint4(wa.x, wb.x, wa.y, wb.y);
            *reinterpret_cast<uint4*>(dst + 2) = make_uint4(wa.z, wb.z, wa.w, wb.w);
        }
        __syncthreads();

#pragma unroll
        for (int kh = 0; kh < 4; kh++) {
            uint2 aL[2], aH[2];
#pragma unroll
            for (int t = 0; t < 2; t++) {
                const uint2* ap = sA + (kh*4 + tq)*APCH + mt + t*16 + gid;
                aL[t] = ap[0];
                aH[t] = ap[8];
            }
            const uint2* bp = sW + (kh*4 + tq)*WPCH + n0 + gid;
#pragma unroll
            for (int j = 0; j < 8; j++) {
                uint2 bb = bp[j*8];
#pragma unroll
                for (int t = 0; t < 2; t++)
                    mma_tf32(acc[t][j], aL[t].x, aH[t].x, aL[t].y, aH[t].y, bb.x, bb.y);
            }
        }
    }

    float* gout = path ? g_v : g_u;
#pragma unroll
    for (int t = 0; t < 2; t++) {
        int p = mt + t*16 + gid;
#pragma unroll
        for (int j = 0; j < 8; j++) {
            int co = n0 + j*8 + tq*2;
            size_t o0 = (((size_t)b*CHAN + co)*HH + h)*WW + p;
            float c0v = acc[t][j][0], c1v = acc[t][j][1];
            float c2v = acc[t][j][2], c3v = acc[t][j][3];
            gout[o0]            = c0v;
            gout[o0 + HWSZ]     = c1v;   // co+1
            gout[o0 + 8]        = c2v;   // p+8
            gout[o0 + HWSZ + 8] = c3v;

            float s0 = c0v + c2v;
            float s1 = c1v + c3v;
            float q0 = c0v*c0v + c2v*c2v;
            float q1 = c1v*c1v + c3v*c3v;
#pragma unroll
            for (int o = 4; o < 32; o <<= 1) {
                s0 += __shfl_xor_sync(0xffffffffu, s0, o);
                s1 += __shfl_xor_sync(0xffffffffu, s1, o);
                q0 += __shfl_xor_sync(0xffffffffu, q0, o);
                q1 += __shfl_xor_sync(0xffffffffu, q1, o);
            }
            if (gid == 0) {
                atomicAdd(&s_s[co],     s0);
                atomicAdd(&s_s[co + 1], s1);
                atomicAdd(&s_q[co],     q0);
                atomicAdd(&s_q[co + 1], q1);
            }
        }
    }
    __syncthreads();
    {
        int soff = 2*CHAN + 2*CHAN*path;
        atomicAdd(&g_stats[soff + tid],        s_s[tid]);
        atomicAdd(&g_stats[soff + CHAN + tid], s_q[tid]);
    }
}

// ---------------- final: out = silu(bn2(u) + bns(v)) ----------------
__global__ void k_final(float* __restrict__ out,
                        const float* __restrict__ g2, const float* __restrict__ be2,
                        const float* __restrict__ gs, const float* __restrict__ bes) {
    int i4 = blockIdx.x * blockDim.x + threadIdx.x;
    size_t base = (size_t)i4 * 4;
    if (base >= (size_t)BATCH*CHAN*HWSZ) return;
    int c = (int)((base >> 12) & 255);

    float mu = g_stats[2*CHAN + c] * (1.f / (float)NHW);
    float vu = g_stats[3*CHAN + c] * (1.f / (float)NHW) - mu*mu;
    float su = g2[c] * rsqrtf(vu + EPSBN);
    float bu = be2[c] - mu * su;

    float mv = g_stats[4*CHAN + c] * (1.f / (float)NHW);
    float vv = g_stats[5*CHAN + c] * (1.f / (float)NHW) - mv*mv;
    float sv = gs[c] * rsqrtf(vv + EPSBN);
    float bv = bes[c] - mv * sv;

    float4 u = *(const float4*)&g_u[base];
    float4 v = *(const float4*)&g_v[base];
    float4 o;
    {
        float z;
        z = fmaf(u.x, su, bu) + fmaf(v.x, sv, bv); o.x = siluf_(z);
        z = fmaf(u.y, su, bu) + fmaf(v.y, sv, bv); o.y = siluf_(z);
        z = fmaf(u.z, su, bu) + fmaf(v.z, sv, bv); o.z = siluf_(z);
        z = fmaf(u.w, su, bu) + fmaf(v.w, sv, bv); o.w = siluf_(z);
    }
    *(float4*)&out[base] = o;
}

// ---------------- launch ----------------
extern "C" void kernel_launch(void* const* d_in, const int* in_sizes, int n_in,
                              void* d_out, int out_size) {
    const float* x        = (const float*)d_in[0];
    const float* dce      = (const float*)d_in[1];
    const float* w_dce    = (const float*)d_in[2];
    const float* b_dce    = (const float*)d_in[3];
    const float* w_ch     = (const float*)d_in[4];
    const float* w_shrink = (const float*)d_in[5];
    const float* b_shrink = (const float*)d_in[6];
    const float* w_expand = (const float*)d_in[7];
    const float* b_expand = (const float*)d_in[8];
    const float* w_conv1  = (const float*)d_in[9];
    const float* g_bn1    = (const float*)d_in[10];
    const float* be_bn1   = (const float*)d_in[11];
    const float* w_conv2  = (const float*)d_in[12];
    const float* g_bn2    = (const float*)d_in[13];
    const float* be_bn2   = (const float*)d_in[14];
    const float* w_sc     = (const float*)d_in[15];
    const float* g_bns    = (const float*)d_in[16];
    const float* be_bns   = (const float*)d_in[17];
    float* out = (float*)d_out;

    cudaFuncSetAttribute(k_conv1_mma, cudaFuncAttributeMaxDynamicSharedMemorySize,
                         CONV_SMEM_BYTES);

    k_zero_stats<<<6, 256>>>();
    k_spatial<<<BATCH*CHAN, 256>>>(x, w_ch);
    k_mod<<<BATCH, 128>>>(dce, w_dce, b_dce, w_shrink, b_shrink, w_expand, b_expand);
    k_transpose<<<256, 256>>>(w_conv2, w_sc);
    k_w1t<<<(9*CHAN*CHAN + 255)/256, 256>>>(w_conv1);
    k_xm<<<(BATCH*CHAN*HWSZ/4 + 255)/256, 256>>>(x);
    k_conv1_mma<<<dim3(32, 2, BATCH), 256, CONV_SMEM_BYTES>>>();
    k_prep<<<(BATCH*CHAN*HWSZ/4 + 255)/256, 256>>>(g_bn1, be_bn1);
    k_gemm_mma2<<<dim3(BATCH*HH, 2), 256>>>();
    k_final<<<(BATCH*CHAN*HWSZ/4 + 255)/256, 256>>>(out, g_bn2, be_bn2, g_bns, be_bns);
}